// round 5
// baseline (speedup 1.0000x reference)
#include <cuda_runtime.h>
#include <limits.h>

// Problem shape (fixed by setup_inputs): B=256, N=65536, half=32768.
#define NCOL   65536
#define HALF   32768
#define BDIM   512
#define NITER  (HALF / (BDIM * 8))    // 8 iterations, 8 elements/thread/iter
#define NSEG8  (HALF / 8)             // 4096 8-element blocks per half
#define MAXB   1024

#define THRESH  0.01f
#define PENALTY 2.0f

__device__ float        g_partials[MAXB];
__device__ unsigned int g_counter = 0;

struct f8 { float v[8]; };

__device__ __forceinline__ f8 ld8(const float* p) {
    unsigned a0,a1,a2,a3,a4,a5,a6,a7;
    asm volatile("ld.global.nc.v8.b32 {%0,%1,%2,%3,%4,%5,%6,%7}, [%8];"
                 : "=r"(a0),"=r"(a1),"=r"(a2),"=r"(a3),
                   "=r"(a4),"=r"(a5),"=r"(a6),"=r"(a7)
                 : "l"(p));
    f8 r;
    r.v[0]=__uint_as_float(a0); r.v[1]=__uint_as_float(a1);
    r.v[2]=__uint_as_float(a2); r.v[3]=__uint_as_float(a3);
    r.v[4]=__uint_as_float(a4); r.v[5]=__uint_as_float(a5);
    r.v[6]=__uint_as_float(a6); r.v[7]=__uint_as_float(a7);
    return r;
}

__global__ __launch_bounds__(BDIM, 2)
void fused_loss_kernel(const float* __restrict__ pred,
                       const float* __restrict__ lab,
                       float* __restrict__ out,
                       int B)
{
    const int b = blockIdx.x;
    const size_t row = (size_t)b * NCOL;

    __shared__ float s_segr[NSEG8];      // per-8-element-block sum of dr^2
    __shared__ float s_segi[NSEG8];      // per-block sum of di^2
    __shared__ int   s_min_r, s_max_r, s_min_i, s_max_i;
    __shared__ int   s_fr, s_lr, s_fi, s_li;
    __shared__ bool  s_is_last;
    if (threadIdx.x == 0) {
        s_min_r = INT_MAX; s_max_r = -1;
        s_min_i = INT_MAX; s_max_i = -1;
    }
    __syncthreads();

    const int lane = threadIdx.x & 31;
    const int warp = threadIdx.x >> 5;

    // ================= SINGLE PASS: everything read exactly once =============
    int tmin_r8 = INT_MAX, tmax_r8 = -1;
    int tmin_i8 = INT_MAX, tmax_i8 = -1;
    float acc = 0.0f;

    #pragma unroll
    for (int it = 0; it < NITER; it++) {
        const int j8 = threadIdx.x + it * BDIM;       // 8-element block index
        const size_t e = (size_t)j8 * 8;
        f8 L  = ld8(lab  + row + e);
        f8 Li = ld8(lab  + row + HALF + e);
        f8 P  = ld8(pred + row + e);
        f8 Pi = ld8(pred + row + HALF + e);

        float sr = 0.0f, si = 0.0f, sq = 0.0f;
        float mxr = 0.0f, mxi = 0.0f;
        #pragma unroll
        for (int k = 0; k < 8; k++) {
            float lrx = L.v[k],  lix = Li.v[k];
            float prx = P.v[k],  pix = Pi.v[k];
            mxr = fmaxf(mxr, fabsf(lrx));
            mxi = fmaxf(mxi, fabsf(lix));
            float dr = prx - lrx;
            float di = pix - lix;
            sr = fmaf(dr, dr, sr);
            si = fmaf(di, di, si);
            float lint = fmaf(lix, lix, lrx * lrx);
            float pint = fmaf(pix, pix, prx * prx);
            float dint = pint - lint;
            sq = fmaf(dint, dint, sq);
        }
        if (mxr > THRESH) { tmin_r8 = min(tmin_r8, j8); tmax_r8 = max(tmax_r8, j8); }
        if (mxi > THRESH) { tmin_i8 = min(tmin_i8, j8); tmax_i8 = max(tmax_i8, j8); }
        s_segr[j8] = sr;
        s_segi[j8] = si;
        acc += sr + si + 50.0f * sq;
    }

    // ---- block-level min/max of significant 8-blocks -------------------------
    #pragma unroll
    for (int off = 16; off > 0; off >>= 1) {
        tmin_r8 = min(tmin_r8, __shfl_xor_sync(0xFFFFFFFFu, tmin_r8, off));
        tmax_r8 = max(tmax_r8, __shfl_xor_sync(0xFFFFFFFFu, tmax_r8, off));
        tmin_i8 = min(tmin_i8, __shfl_xor_sync(0xFFFFFFFFu, tmin_i8, off));
        tmax_i8 = max(tmax_i8, __shfl_xor_sync(0xFFFFFFFFu, tmax_i8, off));
    }
    if (lane == 0) {
        atomicMin(&s_min_r, tmin_r8);
        atomicMax(&s_max_r, tmax_r8);
        atomicMin(&s_min_i, tmin_i8);
        atomicMax(&s_max_i, tmax_i8);
    }
    __syncthreads();   // also covers s_seg* writes

    const int fr8 = (s_max_r < 0) ? 0         : s_min_r;
    const int lr8 = (s_max_r < 0) ? NSEG8 - 1 : s_max_r;
    const int fi8 = (s_max_i < 0) ? 0         : s_min_i;
    const int li8 = (s_max_i < 0) ? NSEG8 - 1 : s_max_i;

    // ---- refine boundary blocks to element-exact first/last (warp 0) --------
    if (threadIdx.x < 32) {
        const int g = threadIdx.x >> 3;            // 0:r-first 1:r-last 2:i-first 3:i-last
        const int u = threadIdx.x & 7;
        const int blk = (g == 0) ? fr8 : (g == 1) ? lr8 : (g == 2) ? fi8 : li8;
        const float* base = lab + row + ((g >= 2) ? HALF : 0);
        float v = base[blk * 8 + u];
        unsigned bal = __ballot_sync(0xFFFFFFFFu, fabsf(v) > THRESH);
        unsigned byt = (bal >> (g * 8)) & 0xFFu;
        if (u == 0) {
            if (g == 0) s_fr = (s_max_r < 0) ? 0        : fr8 * 8 + (__ffs(byt) - 1);
            if (g == 1) s_lr = (s_max_r < 0) ? HALF - 1 : lr8 * 8 + (31 - __clz(byt));
            if (g == 2) s_fi = (s_max_i < 0) ? 0        : fi8 * 8 + (__ffs(byt) - 1);
            if (g == 3) s_li = (s_max_i < 0) ? HALF - 1 : li8 * 8 + (31 - __clz(byt));
        }
    }
    __syncthreads();

    const int fr = s_fr, lr = s_lr, fi = s_fi, li = s_li;

    // ---- correction: (P-1) * sum of dr^2/di^2 outside [first,last] ----------
    float corr = 0.0f;
    #pragma unroll
    for (int e = 0; e < NSEG8 / BDIM; e++) {       // 8 entries per thread
        int s = threadIdx.x + e * BDIM;
        float vr = s_segr[s], vi = s_segi[s];
        if (s < fr8 || s > lr8) corr += vr;        // whole block outside range
        if (s < fi8 || s > li8) corr += vi;
    }
    // element-exact partials inside the 4 boundary blocks (re-read from L2)
    if (threadIdx.x < 32) {
        const int g = threadIdx.x >> 3;
        const int u = threadIdx.x & 7;
        int j; bool act; size_t off;
        if      (g == 0) { j = fr8 * 8 + u; act = (j < fr); off = row + j;        }
        else if (g == 1) { j = lr8 * 8 + u; act = (j > lr); off = row + j;        }
        else if (g == 2) { j = fi8 * 8 + u; act = (j < fi); off = row + HALF + j; }
        else             { j = li8 * 8 + u; act = (j > li); off = row + HALF + j; }
        if (act) {
            float d = pred[off] - lab[off];
            corr += d * d;
        }
    }
    acc += (PENALTY - 1.0f) * corr;

    // ---- block sum reduction -------------------------------------------------
    __shared__ float s_warp[BDIM / 32];
    #pragma unroll
    for (int off = 16; off > 0; off >>= 1)
        acc += __shfl_xor_sync(0xFFFFFFFFu, acc, off);
    if (lane == 0)
        s_warp[warp] = acc;
    __syncthreads();
    if (threadIdx.x < 32) {
        float v = (threadIdx.x < BDIM / 32) ? s_warp[threadIdx.x] : 0.0f;
        #pragma unroll
        for (int off = 16; off > 0; off >>= 1)
            v += __shfl_xor_sync(0xFFFFFFFFu, v, off);
        if (threadIdx.x == 0)
            g_partials[b] = v;
    }

    // ---- last CTA folds the per-row partials (self-resetting for graphs) ----
    if (threadIdx.x == 0) {
        __threadfence();
        unsigned int ticket = atomicAdd(&g_counter, 1u);
        s_is_last = (ticket == (unsigned int)(B - 1));
    }
    __syncthreads();

    if (s_is_last) {
        __threadfence();
        __shared__ float s_fin[256];
        if (threadIdx.x < 256)
            s_fin[threadIdx.x] = (threadIdx.x < B) ? g_partials[threadIdx.x] : 0.0f;
        __syncthreads();
        #pragma unroll
        for (int st = 128; st > 0; st >>= 1) {
            if (threadIdx.x < st) s_fin[threadIdx.x] += s_fin[threadIdx.x + st];
            __syncthreads();
        }
        if (threadIdx.x == 0) {
            out[0] = s_fin[0] / ((float)HALF * (float)B);
            g_counter = 0;
        }
    }
}

extern "C" void kernel_launch(void* const* d_in, const int* in_sizes, int n_in,
                              void* d_out, int out_size)
{
    const float* pred = (const float*)d_in[0];
    const float* lab  = (const float*)d_in[1];
    float* out = (float*)d_out;

    const int B = in_sizes[0] / NCOL;   // 256

    fused_loss_kernel<<<B, BDIM>>>(pred, lab, out, B);
}